// round 1
// baseline (speedup 1.0000x reference)
#include <cuda_runtime.h>

#define NU 100000
#define NI 50000
#define NN 150000
#define DD 64
#define EG 3200000
#define EU_ 1600000
#define EI_ 800000

// ---------------- device scratch (static, no runtime alloc) ----------------
__device__ float g_cur[NN * DD];        // 38.4 MB
__device__ float g_gnn[NN * DD];        // 38.4 MB
__device__ float g_total[NN * DD];      // 38.4 MB
__device__ float g_z[NN * 2 * DD];      // 76.8 MB  (row = node*2 + metapath, user block then item block)
__device__ float g_deg[(NU + NI) * 4];  // user: [(2m+io)*NU + u], item at offset NU*4: [(2m+io)*NI + i]
__device__ float g_wsum[4];             // [0,1]=user mp sums, [2,3]=item mp sums

__device__ __forceinline__ void red_add_v4(float* addr, float4 v) {
    asm volatile("red.global.add.v4.f32 [%0], {%1,%2,%3,%4};"
                 :: "l"(addr), "f"(v.x), "f"(v.y), "f"(v.z), "f"(v.w)
                 : "memory");
}

// ---------------- init / zero ----------------
__global__ void __launch_bounds__(256) k_init(const float* __restrict__ fu,
                                              const float* __restrict__ fi) {
    unsigned i = blockIdx.x * 256u + threadIdx.x;
    if (i < NU * DD) {
        float v = fu[i];
        g_cur[i] = v; g_total[i] = v;
    } else if (i < NN * DD) {
        float v = fi[i - NU * DD];
        g_cur[i] = v; g_total[i] = v;
    }
}

__global__ void __launch_bounds__(256) k_zero_gnn() {
    unsigned i = blockIdx.x * 256u + threadIdx.x;
    if (i < NN * DD) g_gnn[i] = 0.f;
}

__global__ void __launch_bounds__(256) k_zero_han() {
    unsigned i = blockIdx.x * 256u + threadIdx.x;
    if (i < (unsigned)(NN * 2 * DD)) g_z[i] = 0.f;
    if (i < (unsigned)((NU + NI) * 4)) g_deg[i] = 0.f;
    if (i < 4u) g_wsum[i] = 0.f;
}

// ---------------- DCCF: SpMM gnn[row] += val * cur[col] ----------------
__global__ void __launch_bounds__(256) k_spmm(const int* __restrict__ G,
                                              const float* __restrict__ gv) {
    unsigned t = blockIdx.x * 256u + threadIdx.x;
    unsigned e = t >> 4;
    unsigned c = t & 15u;
    if (e >= EG) return;
    int row = __ldg(G + e);
    int col = __ldg(G + EG + e);
    float v = __ldg(gv + e);
    float4 x = *(const float4*)(g_cur + (size_t)col * DD + c * 4);
    red_add_v4(g_gnn + (size_t)row * DD + c * 4,
               make_float4(v * x.x, v * x.y, v * x.z, v * x.w));
}

// ---------------- DCCF: intent projection + residual + total, fused ----------------
// 4 rows per warp, 8 warps/block -> 32 rows/block.
// smem: Wsh4[2048] f4 (W[k][lane*4..+3]) | WT2[4096] f2 ({W[2L][j],W[2L+1][j]})
//       ush[8*256] | psh[8*512]  -> 90112 bytes dynamic
__global__ void __launch_bounds__(256) k_intent(const float* __restrict__ Wu,
                                                const float* __restrict__ Wi) {
    extern __shared__ float sm[];
    float4* Wsh4 = (float4*)sm;            // 8192 floats
    float2* WT2  = (float2*)(sm + 8192);   // 8192 floats
    float*  ush  = sm + 16384;             // 2048 floats
    float*  psh  = sm + 18432;             // 4096 floats

    const int tid = threadIdx.x, w = tid >> 5, lane = tid & 31;
    const int UB = NU / 32;  // 3125 exact
    const bool isUser = (int)blockIdx.x < UB;
    const float* Wg = isUser ? Wu : Wi;
    const int rowbase = isUser ? (int)blockIdx.x * 32 : NU + ((int)blockIdx.x - UB) * 32;
    const int rowlim = isUser ? NU : NN;

    for (int t = tid; t < 2048; t += 256) {
        int k = t >> 5, L = t & 31;
        Wsh4[t] = *(const float4*)(Wg + k * 128 + L * 4);
    }
    for (int t = tid; t < 4096; t += 256) {
        int j = t >> 5, L = t & 31;
        WT2[t] = make_float2(Wg[(2 * L) * 128 + j], Wg[(2 * L + 1) * 128 + j]);
    }
    __syncthreads();

    const int r0 = rowbase + w * 4;
    float* u = ush + w * 256;
    float* p = psh + w * 512;

    for (int t = lane; t < 256; t += 32) {
        int rr = t >> 6, d = t & 63;
        int r = r0 + rr;
        u[t] = (r < rowlim) ? g_cur[(size_t)r * DD + d] : 0.f;
    }
    __syncwarp();

    float acc[4][4];
#pragma unroll
    for (int a = 0; a < 4; a++) {
#pragma unroll
        for (int b = 0; b < 4; b++) acc[a][b] = 0.f;
    }

#pragma unroll 4
    for (int kk = 0; kk < 16; kk++) {
        float4 w0 = Wsh4[(4 * kk + 0) * 32 + lane];
        float4 w1 = Wsh4[(4 * kk + 1) * 32 + lane];
        float4 w2 = Wsh4[(4 * kk + 2) * 32 + lane];
        float4 w3 = Wsh4[(4 * kk + 3) * 32 + lane];
#pragma unroll
        for (int rr = 0; rr < 4; rr++) {
            float4 uv = *(const float4*)(u + rr * 64 + kk * 4);
            acc[rr][0] += uv.x * w0.x + uv.y * w1.x + uv.z * w2.x + uv.w * w3.x;
            acc[rr][1] += uv.x * w0.y + uv.y * w1.y + uv.z * w2.y + uv.w * w3.y;
            acc[rr][2] += uv.x * w0.z + uv.y * w1.z + uv.z * w2.z + uv.w * w3.z;
            acc[rr][3] += uv.x * w0.w + uv.y * w1.w + uv.z * w2.w + uv.w * w3.w;
        }
    }

#pragma unroll
    for (int rr = 0; rr < 4; rr++) {
        float m = fmaxf(fmaxf(acc[rr][0], acc[rr][1]), fmaxf(acc[rr][2], acc[rr][3]));
#pragma unroll
        for (int off = 16; off; off >>= 1) m = fmaxf(m, __shfl_xor_sync(0xffffffffu, m, off));
        float e0 = __expf(acc[rr][0] - m), e1 = __expf(acc[rr][1] - m);
        float e2 = __expf(acc[rr][2] - m), e3 = __expf(acc[rr][3] - m);
        float s = e0 + e1 + e2 + e3;
#pragma unroll
        for (int off = 16; off; off >>= 1) s += __shfl_xor_sync(0xffffffffu, s, off);
        float inv = 1.f / s;
        ((float4*)(p + rr * 128))[lane] = make_float4(e0 * inv, e1 * inv, e2 * inv, e3 * inv);
    }
    __syncwarp();

#pragma unroll
    for (int rr = 0; rr < 4; rr++) {
        int r = r0 + rr;
        if (r >= rowlim) continue;
        float ox = 0.f, oy = 0.f;
        const float4* pv4 = (const float4*)(p + rr * 128);
#pragma unroll 8
        for (int j4 = 0; j4 < 32; j4++) {
            float4 pv = pv4[j4];
            float2 a0 = WT2[(4 * j4 + 0) * 32 + lane];
            float2 a1 = WT2[(4 * j4 + 1) * 32 + lane];
            float2 a2 = WT2[(4 * j4 + 2) * 32 + lane];
            float2 a3 = WT2[(4 * j4 + 3) * 32 + lane];
            ox += pv.x * a0.x + pv.y * a1.x + pv.z * a2.x + pv.w * a3.x;
            oy += pv.x * a0.y + pv.y * a1.y + pv.z * a2.y + pv.w * a3.y;
        }
        size_t base = (size_t)r * DD + lane * 2;
        float c0 = u[rr * 64 + lane * 2];
        float c1 = u[rr * 64 + lane * 2 + 1];
        float n0 = g_gnn[base] + ox + c0;
        float n1 = g_gnn[base + 1] + oy + c1;
        g_cur[base] = n0; g_cur[base + 1] = n1;
        g_total[base] += n0; g_total[base + 1] += n1;
    }
}

// ---------------- HAN: degree counting ----------------
__global__ void __launch_bounds__(256) k_deg(const int* __restrict__ edges, int E2,
                                             int n, int degbase) {
    unsigned t = blockIdx.x * 256u + threadIdx.x;
    if (t >= 2u * (unsigned)E2) return;
    int m = (t >= (unsigned)E2) ? 1 : 0;
    int e = (int)t - m * E2;
    int src = __ldg(edges + (size_t)m * 2 * E2 + e);
    int dst = __ldg(edges + (size_t)m * 2 * E2 + E2 + e);
    atomicAdd(&g_deg[degbase + (2 * m + 0) * n + src], 1.f);
    atomicAdd(&g_deg[degbase + (2 * m + 1) * n + dst], 1.f);
}

// ---------------- HAN: scatter z[dst,m] += h[src] * rsqrt(deg_out[src]) ----------------
__global__ void __launch_bounds__(256) k_scatter(const int* __restrict__ edges, int E2,
                                                 int n, int degbase, int zbase,
                                                 const float* __restrict__ feat) {
    unsigned t = blockIdx.x * 256u + threadIdx.x;
    unsigned idx = t >> 4;
    unsigned c = t & 15u;
    if (idx >= 2u * (unsigned)E2) return;
    int m = (idx >= (unsigned)E2) ? 1 : 0;
    int e = (int)idx - m * E2;
    int src = __ldg(edges + (size_t)m * 2 * E2 + e);
    int dst = __ldg(edges + (size_t)m * 2 * E2 + E2 + e);
    float dout = g_deg[degbase + (2 * m) * n + src];
    float s = dout > 0.f ? rsqrtf(dout) : 0.f;
    float4 x = *(const float4*)(feat + (size_t)src * DD + c * 4);
    red_add_v4(g_z + (size_t)zbase + ((size_t)dst * 2 + m) * DD + c * 4,
               make_float4(x.x * s, x.y * s, x.z * s, x.w * s));
}

// ---------------- HAN: in-degree scale + semantic attention logits ----------------
__global__ void __launch_bounds__(256) k_han_node(const float* __restrict__ W1g,
                                                  const float* __restrict__ b1g,
                                                  const float* __restrict__ w2g,
                                                  int n, int degbase, int zbase, int wbase) {
    __shared__ float Wsm[8192];
    __shared__ float ush[2048];
    __shared__ float bsh[128];
    __shared__ float w2sh[128];
    __shared__ float wacc[2];

    const int tid = threadIdx.x, w = tid >> 5, lane = tid & 31;
    for (int t = tid; t < 2048; t += 256) {
        int k = t >> 5, L = t & 31;
        ((float4*)Wsm)[t] = *(const float4*)(W1g + k * 128 + L * 4);
    }
    if (tid < 128) { bsh[tid] = b1g[tid]; w2sh[tid] = w2g[tid]; }
    if (tid < 2) wacc[tid] = 0.f;
    __syncthreads();

    const int rows = 2 * n;
    const int r0 = (int)blockIdx.x * 32 + w * 4;
    float* u = ush + w * 256;

    for (int t = lane; t < 256; t += 32) {
        int rr = t >> 6, d = t & 63;
        int row = r0 + rr;
        float v = 0.f;
        if (row < rows) {
            int node = row >> 1, m = row & 1;
            float din = g_deg[degbase + (2 * m + 1) * n + node];
            float s = din > 0.f ? rsqrtf(din) : 0.f;
            size_t zi = (size_t)zbase + (size_t)row * DD + d;
            v = g_z[zi] * s;
            g_z[zi] = v;  // persist scaled z for combine
        }
        u[t] = v;
    }
    __syncwarp();

    float acc[4][4];
#pragma unroll
    for (int a = 0; a < 4; a++) {
#pragma unroll
        for (int b = 0; b < 4; b++) acc[a][b] = 0.f;
    }
#pragma unroll 4
    for (int kk = 0; kk < 16; kk++) {
        float4 w0 = ((const float4*)Wsm)[(4 * kk + 0) * 32 + lane];
        float4 w1 = ((const float4*)Wsm)[(4 * kk + 1) * 32 + lane];
        float4 w2 = ((const float4*)Wsm)[(4 * kk + 2) * 32 + lane];
        float4 w3 = ((const float4*)Wsm)[(4 * kk + 3) * 32 + lane];
#pragma unroll
        for (int rr = 0; rr < 4; rr++) {
            float4 uv = *(const float4*)(u + rr * 64 + kk * 4);
            acc[rr][0] += uv.x * w0.x + uv.y * w1.x + uv.z * w2.x + uv.w * w3.x;
            acc[rr][1] += uv.x * w0.y + uv.y * w1.y + uv.z * w2.y + uv.w * w3.y;
            acc[rr][2] += uv.x * w0.z + uv.y * w1.z + uv.z * w2.z + uv.w * w3.z;
            acc[rr][3] += uv.x * w0.w + uv.y * w1.w + uv.z * w2.w + uv.w * w3.w;
        }
    }

#pragma unroll
    for (int rr = 0; rr < 4; rr++) {
        int row = r0 + rr;
        float wl = 0.f;
#pragma unroll
        for (int c = 0; c < 4; c++) {
            int j = lane * 4 + c;
            wl += tanhf(acc[rr][c] + bsh[j]) * w2sh[j];
        }
#pragma unroll
        for (int off = 16; off; off >>= 1) wl += __shfl_xor_sync(0xffffffffu, wl, off);
        if (lane == 0 && row < rows) atomicAdd(&wacc[row & 1], wl);
    }
    __syncthreads();
    if (tid < 2) atomicAdd(&g_wsum[wbase + tid], wacc[tid]);
}

// ---------------- final combine: 0.5*dccf + 0.5*han ----------------
__global__ void __launch_bounds__(256) k_combine(float* __restrict__ out) {
    unsigned i = blockIdx.x * 256u + threadIdx.x;
    if (i >= (unsigned)(NN * DD)) return;
    unsigned node = i >> 6, d = i & 63u;
    float w0, w1;
    size_t zr;
    if (node < NU) {
        w0 = g_wsum[0] * (1.f / NU);
        w1 = g_wsum[1] * (1.f / NU);
        zr = (size_t)node * 128;
    } else {
        w0 = g_wsum[2] * (1.f / NI);
        w1 = g_wsum[3] * (1.f / NI);
        zr = (size_t)NU * 128 + (size_t)(node - NU) * 128;
    }
    float mx = fmaxf(w0, w1);
    float e0 = __expf(w0 - mx), e1 = __expf(w1 - mx);
    float inv = 1.f / (e0 + e1);
    float han = (e0 * inv) * g_z[zr + d] + (e1 * inv) * g_z[zr + 64 + d];
    out[i] = 0.5f * g_total[i] + 0.5f * han;
}

// ---------------- launcher ----------------
extern "C" void kernel_launch(void* const* d_in, const int* in_sizes, int n_in,
                              void* d_out, int out_size) {
    const int*   G    = (const int*)d_in[0];
    const float* Gv   = (const float*)d_in[1];
    const float* fu   = (const float*)d_in[2];
    const float* fi   = (const float*)d_in[3];
    const float* Wu   = (const float*)d_in[4];
    const float* Wi   = (const float*)d_in[5];
    const int*   eu   = (const int*)d_in[6];
    const int*   ei   = (const int*)d_in[7];
    const float* suW1 = (const float*)d_in[8];
    const float* sub1 = (const float*)d_in[9];
    const float* suw2 = (const float*)d_in[10];
    const float* siW1 = (const float*)d_in[11];
    const float* sib1 = (const float*)d_in[12];
    const float* siw2 = (const float*)d_in[13];
    float* out = (float*)d_out;

    cudaFuncSetAttribute(k_intent, cudaFuncAttributeMaxDynamicSharedMemorySize, 90112);

    k_init<<<37500, 256>>>(fu, fi);
    for (int layer = 0; layer < 2; layer++) {
        k_zero_gnn<<<37500, 256>>>();
        k_spmm<<<200000, 256>>>(G, Gv);
        k_intent<<<4688, 256, 90112>>>(Wu, Wi);
    }
    k_zero_han<<<75000, 256>>>();
    k_deg<<<12500, 256>>>(eu, EU_, NU, 0);
    k_deg<<<6250, 256>>>(ei, EI_, NI, NU * 4);
    k_scatter<<<200000, 256>>>(eu, EU_, NU, 0, 0, fu);
    k_scatter<<<100000, 256>>>(ei, EI_, NI, NU * 4, NU * 128, fi);
    k_han_node<<<6250, 256>>>(suW1, sub1, suw2, NU, 0, 0, 0);
    k_han_node<<<3125, 256>>>(siW1, sib1, siw2, NI, NU * 4, NU * 128, 2);
    k_combine<<<37500, 256>>>(out);
}

// round 2
// speedup vs baseline: 1.1845x; 1.1845x over previous
#include <cuda_runtime.h>

#define NU 100000
#define NI 50000
#define NN 150000
#define DD 64
#define EG 3200000
#define EU_ 1600000
#define EI_ 800000

// ---------------- device scratch ----------------
__device__ float g_cur[NN * DD];
__device__ float g_gnn[NN * DD];
__device__ float g_total[NN * DD];
__device__ float g_z[NN * 2 * DD];      // row = node*2 + metapath; user block then item block
__device__ float g_deg[(NU + NI) * 4];
__device__ float g_wsum[4];

__device__ __forceinline__ void red_add_v4(float* addr, float4 v) {
    asm volatile("red.global.add.v4.f32 [%0], {%1,%2,%3,%4};"
                 :: "l"(addr), "f"(v.x), "f"(v.y), "f"(v.z), "f"(v.w)
                 : "memory");
}

// ---------------- init / zero ----------------
__global__ void __launch_bounds__(256) k_init(const float* __restrict__ fu,
                                              const float* __restrict__ fi) {
    unsigned i = blockIdx.x * 256u + threadIdx.x;
    if (i < NU * DD) {
        float v = fu[i];
        g_cur[i] = v; g_total[i] = v;
    } else if (i < NN * DD) {
        float v = fi[i - NU * DD];
        g_cur[i] = v; g_total[i] = v;
    }
}

__global__ void __launch_bounds__(256) k_zero_gnn() {
    unsigned i = blockIdx.x * 256u + threadIdx.x;
    if (i < NN * DD) g_gnn[i] = 0.f;
}

__global__ void __launch_bounds__(256) k_zero_han() {
    unsigned i = blockIdx.x * 256u + threadIdx.x;
    if (i < (unsigned)(NN * 2 * DD)) g_z[i] = 0.f;
    if (i < (unsigned)((NU + NI) * 4)) g_deg[i] = 0.f;
    if (i < 4u) g_wsum[i] = 0.f;
}

// ---------------- DCCF: SpMM gnn[row] += val * cur[col] ----------------
__global__ void __launch_bounds__(256) k_spmm(const int* __restrict__ G,
                                              const float* __restrict__ gv) {
    unsigned t = blockIdx.x * 256u + threadIdx.x;
    unsigned e = t >> 4;
    unsigned c = t & 15u;
    if (e >= EG) return;
    int row = __ldg(G + e);
    int col = __ldg(G + EG + e);
    float v = __ldg(gv + e);
    float4 x = *(const float4*)(g_cur + (size_t)col * DD + c * 4);
    red_add_v4(g_gnn + (size_t)row * DD + c * 4,
               make_float4(v * x.x, v * x.y, v * x.z, v * x.w));
}

// ---------------- DCCF: intent projection, 8 rows/warp, broadcast-heavy ----------------
// smem layout (floats):
//   Wsh4  [0     .. 8192)   W[k][4L..4L+3] as float4 at k*32+L
//   WT2   [8192  .. 16384)  (W[2L][j], W[2L+1][j]) as float2 at j*32+L
//   ush   [16384 .. 20480)  8 warps * 8 rows * 64
//   psh   [20480 .. 28672)  8 warps * 8 rows * 128
// total 28672 floats = 114688 bytes
#define INTENT_SMEM 114688
__global__ void __launch_bounds__(256) k_intent(const float* __restrict__ Wu,
                                                const float* __restrict__ Wi) {
    extern __shared__ float sm[];
    float4* Wsh4 = (float4*)sm;
    float2* WT2  = (float2*)(sm + 8192);
    float*  ush  = sm + 16384;
    float*  psh  = sm + 20480;

    const int tid = threadIdx.x, w = tid >> 5, lane = tid & 31;
    const int UB = (NU + 63) / 64;  // 1563
    const bool isUser = (int)blockIdx.x < UB;
    const float* Wg = isUser ? Wu : Wi;
    const int rowbase = isUser ? (int)blockIdx.x * 64 : NU + ((int)blockIdx.x - UB) * 64;
    const int rowlim = isUser ? NU : NN;

    for (int t = tid; t < 2048; t += 256) {
        int k = t >> 5, L = t & 31;
        Wsh4[t] = *(const float4*)(Wg + k * 128 + L * 4);
    }
    for (int t = tid; t < 4096; t += 256) {
        int j = t >> 5, L = t & 31;
        WT2[t] = make_float2(Wg[(2 * L) * 128 + j], Wg[(2 * L + 1) * 128 + j]);
    }
    __syncthreads();

    const int r0 = rowbase + w * 8;
    float* u = ush + w * 512;
    float* p = psh + w * 1024;

    for (int t = lane; t < 512; t += 32) {
        int rr = t >> 6, d = t & 63;
        int r = r0 + rr;
        u[t] = (r < rowlim) ? g_cur[(size_t)r * DD + d] : 0.f;
    }
    __syncwarp();

    // ---- pass 1: scores = u @ W  (lane owns intents 4L..4L+3) ----
    float acc[8][4];
#pragma unroll
    for (int a = 0; a < 8; a++) { acc[a][0] = acc[a][1] = acc[a][2] = acc[a][3] = 0.f; }

#pragma unroll 2
    for (int kk = 0; kk < 16; kk++) {
        float4 w0 = Wsh4[(4 * kk + 0) * 32 + lane];
        float4 w1 = Wsh4[(4 * kk + 1) * 32 + lane];
        float4 w2 = Wsh4[(4 * kk + 2) * 32 + lane];
        float4 w3 = Wsh4[(4 * kk + 3) * 32 + lane];
#pragma unroll
        for (int rr = 0; rr < 8; rr++) {
            float4 uv = *(const float4*)(u + rr * 64 + kk * 4);  // uniform -> broadcast
            acc[rr][0] += uv.x * w0.x + uv.y * w1.x + uv.z * w2.x + uv.w * w3.x;
            acc[rr][1] += uv.x * w0.y + uv.y * w1.y + uv.z * w2.y + uv.w * w3.y;
            acc[rr][2] += uv.x * w0.z + uv.y * w1.z + uv.z * w2.z + uv.w * w3.z;
            acc[rr][3] += uv.x * w0.w + uv.y * w1.w + uv.z * w2.w + uv.w * w3.w;
        }
    }

    // ---- softmax per row, write p to smem ----
#pragma unroll
    for (int rr = 0; rr < 8; rr++) {
        float m = fmaxf(fmaxf(acc[rr][0], acc[rr][1]), fmaxf(acc[rr][2], acc[rr][3]));
#pragma unroll
        for (int off = 16; off; off >>= 1) m = fmaxf(m, __shfl_xor_sync(0xffffffffu, m, off));
        float e0 = __expf(acc[rr][0] - m), e1 = __expf(acc[rr][1] - m);
        float e2 = __expf(acc[rr][2] - m), e3 = __expf(acc[rr][3] - m);
        float s = e0 + e1 + e2 + e3;
#pragma unroll
        for (int off = 16; off; off >>= 1) s += __shfl_xor_sync(0xffffffffu, s, off);
        float inv = 1.f / s;
        ((float4*)(p + rr * 128))[lane] = make_float4(e0 * inv, e1 * inv, e2 * inv, e3 * inv);
    }
    __syncwarp();

    // ---- pass 2: out = p @ W^T  (lane owns dims 2L, 2L+1) ----
    float ox[8], oy[8];
#pragma unroll
    for (int rr = 0; rr < 8; rr++) { ox[rr] = 0.f; oy[rr] = 0.f; }

#pragma unroll 2
    for (int j4 = 0; j4 < 32; j4++) {
        float2 a0 = WT2[(4 * j4 + 0) * 32 + lane];
        float2 a1 = WT2[(4 * j4 + 1) * 32 + lane];
        float2 a2 = WT2[(4 * j4 + 2) * 32 + lane];
        float2 a3 = WT2[(4 * j4 + 3) * 32 + lane];
#pragma unroll
        for (int rr = 0; rr < 8; rr++) {
            float4 pv = *(const float4*)(p + rr * 128 + j4 * 4);  // uniform -> broadcast
            ox[rr] += pv.x * a0.x + pv.y * a1.x + pv.z * a2.x + pv.w * a3.x;
            oy[rr] += pv.x * a0.y + pv.y * a1.y + pv.z * a2.y + pv.w * a3.y;
        }
    }

#pragma unroll
    for (int rr = 0; rr < 8; rr++) {
        int r = r0 + rr;
        if (r >= rowlim) continue;
        size_t base = (size_t)r * DD + lane * 2;
        float c0 = u[rr * 64 + lane * 2];
        float c1 = u[rr * 64 + lane * 2 + 1];
        float n0 = g_gnn[base] + ox[rr] + c0;
        float n1 = g_gnn[base + 1] + oy[rr] + c1;
        g_cur[base] = n0; g_cur[base + 1] = n1;
        g_total[base] += n0; g_total[base + 1] += n1;
    }
}

// ---------------- HAN: degree counting ----------------
__global__ void __launch_bounds__(256) k_deg(const int* __restrict__ edges, int E2,
                                             int n, int degbase) {
    unsigned t = blockIdx.x * 256u + threadIdx.x;
    if (t >= 2u * (unsigned)E2) return;
    int m = (t >= (unsigned)E2) ? 1 : 0;
    int e = (int)t - m * E2;
    int src = __ldg(edges + (size_t)m * 2 * E2 + e);
    int dst = __ldg(edges + (size_t)m * 2 * E2 + E2 + e);
    atomicAdd(&g_deg[degbase + (2 * m + 0) * n + src], 1.f);
    atomicAdd(&g_deg[degbase + (2 * m + 1) * n + dst], 1.f);
}

// ---------------- HAN: scatter z[dst,m] += h[src] * rsqrt(deg_out[src]) ----------------
__global__ void __launch_bounds__(256) k_scatter(const int* __restrict__ edges, int E2,
                                                 int n, int degbase, int zbase,
                                                 const float* __restrict__ feat) {
    unsigned t = blockIdx.x * 256u + threadIdx.x;
    unsigned idx = t >> 4;
    unsigned c = t & 15u;
    if (idx >= 2u * (unsigned)E2) return;
    int m = (idx >= (unsigned)E2) ? 1 : 0;
    int e = (int)idx - m * E2;
    int src = __ldg(edges + (size_t)m * 2 * E2 + e);
    int dst = __ldg(edges + (size_t)m * 2 * E2 + E2 + e);
    float dout = g_deg[degbase + (2 * m) * n + src];
    float s = dout > 0.f ? rsqrtf(dout) : 0.f;
    float4 x = *(const float4*)(feat + (size_t)src * DD + c * 4);
    red_add_v4(g_z + (size_t)zbase + ((size_t)dst * 2 + m) * DD + c * 4,
               make_float4(x.x * s, x.y * s, x.z * s, x.w * s));
}

// ---------------- HAN: in-degree scale + semantic attention logits, 8 rows/warp ----------------
__global__ void __launch_bounds__(256) k_han_node(const float* __restrict__ W1g,
                                                  const float* __restrict__ b1g,
                                                  const float* __restrict__ w2g,
                                                  int n, int degbase, int zbase, int wbase) {
    __shared__ float Wsm[8192];
    __shared__ float ush[4096];   // 8 warps * 8 rows * 64
    __shared__ float bsh[128];
    __shared__ float w2sh[128];
    __shared__ float wacc[2];

    const int tid = threadIdx.x, w = tid >> 5, lane = tid & 31;
    for (int t = tid; t < 2048; t += 256) {
        int k = t >> 5, L = t & 31;
        ((float4*)Wsm)[t] = *(const float4*)(W1g + k * 128 + L * 4);
    }
    if (tid < 128) { bsh[tid] = b1g[tid]; w2sh[tid] = w2g[tid]; }
    if (tid < 2) wacc[tid] = 0.f;
    __syncthreads();

    const int rows = 2 * n;
    const int r0 = (int)blockIdx.x * 64 + w * 8;
    float* u = ush + w * 512;

    for (int t = lane; t < 512; t += 32) {
        int rr = t >> 6, d = t & 63;
        int row = r0 + rr;
        float v = 0.f;
        if (row < rows) {
            int node = row >> 1, m = row & 1;
            float din = g_deg[degbase + (2 * m + 1) * n + node];
            float s = din > 0.f ? rsqrtf(din) : 0.f;
            size_t zi = (size_t)zbase + (size_t)row * DD + d;
            v = g_z[zi] * s;
            g_z[zi] = v;  // persist scaled z for combine
        }
        u[t] = v;
    }
    __syncwarp();

    float acc[8][4];
#pragma unroll
    for (int a = 0; a < 8; a++) { acc[a][0] = acc[a][1] = acc[a][2] = acc[a][3] = 0.f; }

#pragma unroll 2
    for (int kk = 0; kk < 16; kk++) {
        float4 w0 = ((const float4*)Wsm)[(4 * kk + 0) * 32 + lane];
        float4 w1 = ((const float4*)Wsm)[(4 * kk + 1) * 32 + lane];
        float4 w2 = ((const float4*)Wsm)[(4 * kk + 2) * 32 + lane];
        float4 w3 = ((const float4*)Wsm)[(4 * kk + 3) * 32 + lane];
#pragma unroll
        for (int rr = 0; rr < 8; rr++) {
            float4 uv = *(const float4*)(u + rr * 64 + kk * 4);
            acc[rr][0] += uv.x * w0.x + uv.y * w1.x + uv.z * w2.x + uv.w * w3.x;
            acc[rr][1] += uv.x * w0.y + uv.y * w1.y + uv.z * w2.y + uv.w * w3.y;
            acc[rr][2] += uv.x * w0.z + uv.y * w1.z + uv.z * w2.z + uv.w * w3.z;
            acc[rr][3] += uv.x * w0.w + uv.y * w1.w + uv.z * w2.w + uv.w * w3.w;
        }
    }

    float wl01[2] = {0.f, 0.f};
#pragma unroll
    for (int rr = 0; rr < 8; rr++) {
        int row = r0 + rr;
        float wl = 0.f;
#pragma unroll
        for (int c = 0; c < 4; c++) {
            int j = lane * 4 + c;
            wl += tanhf(acc[rr][c] + bsh[j]) * w2sh[j];
        }
        if (row < rows) wl01[row & 1] += wl;
    }
#pragma unroll
    for (int off = 16; off; off >>= 1) {
        wl01[0] += __shfl_xor_sync(0xffffffffu, wl01[0], off);
        wl01[1] += __shfl_xor_sync(0xffffffffu, wl01[1], off);
    }
    if (lane == 0) {
        atomicAdd(&wacc[0], wl01[0]);
        atomicAdd(&wacc[1], wl01[1]);
    }
    __syncthreads();
    if (tid < 2) atomicAdd(&g_wsum[wbase + tid], wacc[tid]);
}

// ---------------- final combine: 0.5*dccf + 0.5*han ----------------
__global__ void __launch_bounds__(256) k_combine(float* __restrict__ out) {
    unsigned i = blockIdx.x * 256u + threadIdx.x;
    if (i >= (unsigned)(NN * DD)) return;
    unsigned node = i >> 6, d = i & 63u;
    float w0, w1;
    size_t zr;
    if (node < NU) {
        w0 = g_wsum[0] * (1.f / NU);
        w1 = g_wsum[1] * (1.f / NU);
        zr = (size_t)node * 128;
    } else {
        w0 = g_wsum[2] * (1.f / NI);
        w1 = g_wsum[3] * (1.f / NI);
        zr = (size_t)NU * 128 + (size_t)(node - NU) * 128;
    }
    float mx = fmaxf(w0, w1);
    float e0 = __expf(w0 - mx), e1 = __expf(w1 - mx);
    float inv = 1.f / (e0 + e1);
    float han = (e0 * inv) * g_z[zr + d] + (e1 * inv) * g_z[zr + 64 + d];
    out[i] = 0.5f * g_total[i] + 0.5f * han;
}

// ---------------- launcher ----------------
extern "C" void kernel_launch(void* const* d_in, const int* in_sizes, int n_in,
                              void* d_out, int out_size) {
    const int*   G    = (const int*)d_in[0];
    const float* Gv   = (const float*)d_in[1];
    const float* fu   = (const float*)d_in[2];
    const float* fi   = (const float*)d_in[3];
    const float* Wu   = (const float*)d_in[4];
    const float* Wi   = (const float*)d_in[5];
    const int*   eu   = (const int*)d_in[6];
    const int*   ei   = (const int*)d_in[7];
    const float* suW1 = (const float*)d_in[8];
    const float* sub1 = (const float*)d_in[9];
    const float* suw2 = (const float*)d_in[10];
    const float* siW1 = (const float*)d_in[11];
    const float* sib1 = (const float*)d_in[12];
    const float* siw2 = (const float*)d_in[13];
    float* out = (float*)d_out;

    cudaFuncSetAttribute(k_intent, cudaFuncAttributeMaxDynamicSharedMemorySize, INTENT_SMEM);

    const int UB = (NU + 63) / 64;      // 1563
    const int IB = (NI + 63) / 64;      // 782

    k_init<<<37500, 256>>>(fu, fi);
    for (int layer = 0; layer < 2; layer++) {
        k_zero_gnn<<<37500, 256>>>();
        k_spmm<<<200000, 256>>>(G, Gv);
        k_intent<<<UB + IB, 256, INTENT_SMEM>>>(Wu, Wi);
    }
    k_zero_han<<<75000, 256>>>();
    k_deg<<<12500, 256>>>(eu, EU_, NU, 0);
    k_deg<<<6250, 256>>>(ei, EI_, NI, NU * 4);
    k_scatter<<<200000, 256>>>(eu, EU_, NU, 0, 0, fu);
    k_scatter<<<100000, 256>>>(ei, EI_, NI, NU * 4, NU * 128, fi);
    k_han_node<<<3125, 256>>>(suW1, sub1, suw2, NU, 0, 0, 0);
    k_han_node<<<1563, 256>>>(siW1, sib1, siw2, NI, NU * 4, NU * 128, 2);
    k_combine<<<37500, 256>>>(out);
}

// round 3
// speedup vs baseline: 1.2036x; 1.0161x over previous
#include <cuda_runtime.h>

#define NU 100000
#define NI 50000
#define NN 150000
#define DD 64
#define EG 3200000
#define EU_ 1600000
#define EI_ 800000

// ---------------- device scratch ----------------
__device__ float g_cur[NN * DD];
__device__ float g_gnn[NN * DD];
__device__ float g_total[NN * DD];
__device__ float g_z[NN * 2 * DD];      // row = node*2 + metapath; user block then item block
__device__ float g_deg[(NU + NI) * 4];
__device__ float g_wsum[4];

__device__ __forceinline__ void red_add_v4(float* addr, float4 v) {
    asm volatile("red.global.add.v4.f32 [%0], {%1,%2,%3,%4};"
                 :: "l"(addr), "f"(v.x), "f"(v.y), "f"(v.z), "f"(v.w)
                 : "memory");
}

// f32x2 packed math (sm_100+ PTX)
__device__ __forceinline__ unsigned long long pk2(float a) {
    unsigned long long r;
    asm("mov.b64 %0, {%1, %1};" : "=l"(r) : "f"(a));
    return r;
}
__device__ __forceinline__ void fma2(unsigned long long& d, unsigned long long a,
                                     unsigned long long b) {
    asm("fma.rn.f32x2 %0, %1, %2, %0;" : "+l"(d) : "l"(a), "l"(b));
}
__device__ __forceinline__ float2 up2(unsigned long long v) {
    float2 f;
    asm("mov.b64 {%0, %1}, %2;" : "=f"(f.x), "=f"(f.y) : "l"(v));
    return f;
}

// ---------------- init / zero ----------------
__global__ void __launch_bounds__(256) k_init(const float* __restrict__ fu,
                                              const float* __restrict__ fi) {
    unsigned i = blockIdx.x * 256u + threadIdx.x;
    if (i < NU * DD) {
        float v = fu[i];
        g_cur[i] = v; g_total[i] = v;
    } else if (i < NN * DD) {
        float v = fi[i - NU * DD];
        g_cur[i] = v; g_total[i] = v;
    }
}

__global__ void __launch_bounds__(256) k_zero_gnn() {
    unsigned i = blockIdx.x * 256u + threadIdx.x;
    if (i < NN * DD) g_gnn[i] = 0.f;
}

__global__ void __launch_bounds__(256) k_zero_han() {
    unsigned i = blockIdx.x * 256u + threadIdx.x;
    if (i < (unsigned)(NN * 2 * DD)) g_z[i] = 0.f;
    if (i < (unsigned)((NU + NI) * 4)) g_deg[i] = 0.f;
    if (i < 4u) g_wsum[i] = 0.f;
}

// ---------------- DCCF: SpMM gnn[row] += val * cur[col] ----------------
__global__ void __launch_bounds__(256) k_spmm(const int* __restrict__ G,
                                              const float* __restrict__ gv) {
    unsigned t = blockIdx.x * 256u + threadIdx.x;
    unsigned e = t >> 4;
    unsigned c = t & 15u;
    if (e >= EG) return;
    int row = __ldg(G + e);
    int col = __ldg(G + EG + e);
    float v = __ldg(gv + e);
    float4 x = *(const float4*)(g_cur + (size_t)col * DD + c * 4);
    red_add_v4(g_gnn + (size_t)row * DD + c * 4,
               make_float4(v * x.x, v * x.y, v * x.z, v * x.w));
}

// ---------------- DCCF: intent projection, f32x2, 4 rows/warp, 384 thr ----------------
// smem (floats):
//   Wp  [0     .. 8192)   float4 {W[k][2L],W[k][2L+1],W[k][64+2L],W[k][65+2L]} @ k*32+L
//   WT  [8192  .. 16384)  float4 {Wt(j)=|W[2L][j],W[2L+1][j]| for j=2j2, j=2j2+1} @ j2*32+L
//   ush [16384 .. 19456)  12 warps * 4 rows * 64
//   psh [19456 .. 25600)  12 warps * 4 rows * 128
// 25600 floats = 102400 bytes
#define INTENT_SMEM 102400
#define IT_THREADS 384
#define IT_ROWS_PER_BLOCK 48

__global__ void __launch_bounds__(IT_THREADS, 2) k_intent(const float* __restrict__ Wu,
                                                          const float* __restrict__ Wi) {
    extern __shared__ float sm[];
    const ulonglong2* Wp2 = (const ulonglong2*)sm;
    const ulonglong2* WT2 = (const ulonglong2*)(sm + 8192);
    float* ush = sm + 16384;
    float* psh = sm + 19456;

    const int tid = threadIdx.x, w = tid >> 5, lane = tid & 31;
    const int UB = (NU + IT_ROWS_PER_BLOCK - 1) / IT_ROWS_PER_BLOCK;  // 2084
    const bool isUser = (int)blockIdx.x < UB;
    const float* Wg = isUser ? Wu : Wi;
    const int rowbase = isUser ? (int)blockIdx.x * IT_ROWS_PER_BLOCK
                               : NU + ((int)blockIdx.x - UB) * IT_ROWS_PER_BLOCK;
    const int rowlim = isUser ? NU : NN;

    // fill Wp: pass-1 layout (k-major, intent pairs per lane)
    for (int t = tid; t < 2048; t += IT_THREADS) {
        int k = t >> 5, L = t & 31;
        float2 a = *(const float2*)(Wg + k * 128 + 2 * L);
        float2 b = *(const float2*)(Wg + k * 128 + 64 + 2 * L);
        ((float4*)sm)[t] = make_float4(a.x, a.y, b.x, b.y);
    }
    // fill WT: pass-2 layout (j-major, dim pairs per lane)
    for (int t = tid; t < 2048; t += IT_THREADS) {
        int j2 = t >> 5, L = t & 31;
        float x0 = Wg[(2 * L) * 128 + 2 * j2];
        float y0 = Wg[(2 * L + 1) * 128 + 2 * j2];
        float x1 = Wg[(2 * L) * 128 + 2 * j2 + 1];
        float y1 = Wg[(2 * L + 1) * 128 + 2 * j2 + 1];
        ((float4*)(sm + 8192))[t] = make_float4(x0, y0, x1, y1);
    }
    __syncthreads();

    const int r0 = rowbase + w * 4;
    float* u = ush + w * 256;
    float* p = psh + w * 512;

    for (int t = lane; t < 256; t += 32) {
        int rr = t >> 6, d = t & 63;
        int r = r0 + rr;
        u[t] = (r < rowlim) ? g_cur[(size_t)r * DD + d] : 0.f;
    }
    __syncwarp();

    // ---- pass 1: scores = u @ W.  acc[r][g]: f32x2 over intents (2L,2L+1)+(g?64:0)
    unsigned long long acc[4][2];
#pragma unroll
    for (int r = 0; r < 4; r++) { acc[r][0] = 0ull; acc[r][1] = 0ull; }

#pragma unroll 4
    for (int kk = 0; kk < 16; kk++) {
        ulonglong2 wv0 = Wp2[(4 * kk + 0) * 32 + lane];
        ulonglong2 wv1 = Wp2[(4 * kk + 1) * 32 + lane];
        ulonglong2 wv2 = Wp2[(4 * kk + 2) * 32 + lane];
        ulonglong2 wv3 = Wp2[(4 * kk + 3) * 32 + lane];
        float4 uv0 = *(const float4*)(u + 0 * 64 + kk * 4);
        float4 uv1 = *(const float4*)(u + 1 * 64 + kk * 4);
        float4 uv2 = *(const float4*)(u + 2 * 64 + kk * 4);
        float4 uv3 = *(const float4*)(u + 3 * 64 + kk * 4);
#define P1STEP(WV, CMP)                                              \
        {                                                            \
            unsigned long long s0 = pk2(uv0.CMP);                    \
            unsigned long long s1 = pk2(uv1.CMP);                    \
            unsigned long long s2 = pk2(uv2.CMP);                    \
            unsigned long long s3 = pk2(uv3.CMP);                    \
            fma2(acc[0][0], WV.x, s0); fma2(acc[0][1], WV.y, s0);    \
            fma2(acc[1][0], WV.x, s1); fma2(acc[1][1], WV.y, s1);    \
            fma2(acc[2][0], WV.x, s2); fma2(acc[2][1], WV.y, s2);    \
            fma2(acc[3][0], WV.x, s3); fma2(acc[3][1], WV.y, s3);    \
        }
        P1STEP(wv0, x) P1STEP(wv1, y) P1STEP(wv2, z) P1STEP(wv3, w)
#undef P1STEP
    }

    // ---- softmax per row (lane owns intents 2L,2L+1,64+2L,65+2L) ----
#pragma unroll
    for (int rr = 0; rr < 4; rr++) {
        float2 a = up2(acc[rr][0]);
        float2 b = up2(acc[rr][1]);
        float m = fmaxf(fmaxf(a.x, a.y), fmaxf(b.x, b.y));
#pragma unroll
        for (int off = 16; off; off >>= 1) m = fmaxf(m, __shfl_xor_sync(0xffffffffu, m, off));
        float e0 = __expf(a.x - m), e1 = __expf(a.y - m);
        float e2 = __expf(b.x - m), e3 = __expf(b.y - m);
        float s = e0 + e1 + e2 + e3;
#pragma unroll
        for (int off = 16; off; off >>= 1) s += __shfl_xor_sync(0xffffffffu, s, off);
        float inv = 1.f / s;
        *(float2*)(p + rr * 128 + 2 * lane) = make_float2(e0 * inv, e1 * inv);
        *(float2*)(p + rr * 128 + 64 + 2 * lane) = make_float2(e2 * inv, e3 * inv);
    }
    __syncwarp();

    // ---- pass 2: out = p @ W^T.  acc2[r]: f32x2 over dims (2L, 2L+1) ----
    unsigned long long acc2[4];
#pragma unroll
    for (int r = 0; r < 4; r++) acc2[r] = 0ull;

#pragma unroll 8
    for (int g = 0; g < 32; g++) {
        ulonglong2 wt0 = WT2[(2 * g + 0) * 32 + lane];  // j = 4g, 4g+1
        ulonglong2 wt1 = WT2[(2 * g + 1) * 32 + lane];  // j = 4g+2, 4g+3
        float4 pv0 = *(const float4*)(p + 0 * 128 + g * 4);
        float4 pv1 = *(const float4*)(p + 1 * 128 + g * 4);
        float4 pv2 = *(const float4*)(p + 2 * 128 + g * 4);
        float4 pv3 = *(const float4*)(p + 3 * 128 + g * 4);
#define P2ROW(R, PV)                                        \
        fma2(acc2[R], wt0.x, pk2(PV.x));                    \
        fma2(acc2[R], wt0.y, pk2(PV.y));                    \
        fma2(acc2[R], wt1.x, pk2(PV.z));                    \
        fma2(acc2[R], wt1.y, pk2(PV.w));
        P2ROW(0, pv0) P2ROW(1, pv1) P2ROW(2, pv2) P2ROW(3, pv3)
#undef P2ROW
    }

#pragma unroll
    for (int rr = 0; rr < 4; rr++) {
        int r = r0 + rr;
        if (r >= rowlim) continue;
        float2 o = up2(acc2[rr]);
        size_t base = (size_t)r * DD + lane * 2;
        float c0 = u[rr * 64 + lane * 2];
        float c1 = u[rr * 64 + lane * 2 + 1];
        float n0 = g_gnn[base] + o.x + c0;
        float n1 = g_gnn[base + 1] + o.y + c1;
        g_cur[base] = n0; g_cur[base + 1] = n1;
        g_total[base] += n0; g_total[base + 1] += n1;
    }
}

// ---------------- HAN: degree counting ----------------
__global__ void __launch_bounds__(256) k_deg(const int* __restrict__ edges, int E2,
                                             int n, int degbase) {
    unsigned t = blockIdx.x * 256u + threadIdx.x;
    if (t >= 2u * (unsigned)E2) return;
    int m = (t >= (unsigned)E2) ? 1 : 0;
    int e = (int)t - m * E2;
    int src = __ldg(edges + (size_t)m * 2 * E2 + e);
    int dst = __ldg(edges + (size_t)m * 2 * E2 + E2 + e);
    atomicAdd(&g_deg[degbase + (2 * m + 0) * n + src], 1.f);
    atomicAdd(&g_deg[degbase + (2 * m + 1) * n + dst], 1.f);
}

// ---------------- HAN: scatter z[dst,m] += h[src] * rsqrt(deg_out[src]) ----------------
__global__ void __launch_bounds__(256) k_scatter(const int* __restrict__ edges, int E2,
                                                 int n, int degbase, int zbase,
                                                 const float* __restrict__ feat) {
    unsigned t = blockIdx.x * 256u + threadIdx.x;
    unsigned idx = t >> 4;
    unsigned c = t & 15u;
    if (idx >= 2u * (unsigned)E2) return;
    int m = (idx >= (unsigned)E2) ? 1 : 0;
    int e = (int)idx - m * E2;
    int src = __ldg(edges + (size_t)m * 2 * E2 + e);
    int dst = __ldg(edges + (size_t)m * 2 * E2 + E2 + e);
    float dout = g_deg[degbase + (2 * m) * n + src];
    float s = dout > 0.f ? rsqrtf(dout) : 0.f;
    float4 x = *(const float4*)(feat + (size_t)src * DD + c * 4);
    red_add_v4(g_z + (size_t)zbase + ((size_t)dst * 2 + m) * DD + c * 4,
               make_float4(x.x * s, x.y * s, x.z * s, x.w * s));
}

// ---------------- HAN: in-degree scale + semantic attention logits, 8 rows/warp ----------------
__global__ void __launch_bounds__(256) k_han_node(const float* __restrict__ W1g,
                                                  const float* __restrict__ b1g,
                                                  const float* __restrict__ w2g,
                                                  int n, int degbase, int zbase, int wbase) {
    __shared__ float Wsm[8192];
    __shared__ float ush[4096];   // 8 warps * 8 rows * 64
    __shared__ float bsh[128];
    __shared__ float w2sh[128];
    __shared__ float wacc[2];

    const int tid = threadIdx.x, w = tid >> 5, lane = tid & 31;
    for (int t = tid; t < 2048; t += 256) {
        int k = t >> 5, L = t & 31;
        ((float4*)Wsm)[t] = *(const float4*)(W1g + k * 128 + L * 4);
    }
    if (tid < 128) { bsh[tid] = b1g[tid]; w2sh[tid] = w2g[tid]; }
    if (tid < 2) wacc[tid] = 0.f;
    __syncthreads();

    const int rows = 2 * n;
    const int r0 = (int)blockIdx.x * 64 + w * 8;
    float* u = ush + w * 512;

    for (int t = lane; t < 512; t += 32) {
        int rr = t >> 6, d = t & 63;
        int row = r0 + rr;
        float v = 0.f;
        if (row < rows) {
            int node = row >> 1, m = row & 1;
            float din = g_deg[degbase + (2 * m + 1) * n + node];
            float s = din > 0.f ? rsqrtf(din) : 0.f;
            size_t zi = (size_t)zbase + (size_t)row * DD + d;
            v = g_z[zi] * s;
            g_z[zi] = v;  // persist scaled z for combine
        }
        u[t] = v;
    }
    __syncwarp();

    float acc[8][4];
#pragma unroll
    for (int a = 0; a < 8; a++) { acc[a][0] = acc[a][1] = acc[a][2] = acc[a][3] = 0.f; }

#pragma unroll 2
    for (int kk = 0; kk < 16; kk++) {
        float4 w0 = ((const float4*)Wsm)[(4 * kk + 0) * 32 + lane];
        float4 w1 = ((const float4*)Wsm)[(4 * kk + 1) * 32 + lane];
        float4 w2 = ((const float4*)Wsm)[(4 * kk + 2) * 32 + lane];
        float4 w3 = ((const float4*)Wsm)[(4 * kk + 3) * 32 + lane];
#pragma unroll
        for (int rr = 0; rr < 8; rr++) {
            float4 uv = *(const float4*)(u + rr * 64 + kk * 4);
            acc[rr][0] += uv.x * w0.x + uv.y * w1.x + uv.z * w2.x + uv.w * w3.x;
            acc[rr][1] += uv.x * w0.y + uv.y * w1.y + uv.z * w2.y + uv.w * w3.y;
            acc[rr][2] += uv.x * w0.z + uv.y * w1.z + uv.z * w2.z + uv.w * w3.z;
            acc[rr][3] += uv.x * w0.w + uv.y * w1.w + uv.z * w2.w + uv.w * w3.w;
        }
    }

    float wl01[2] = {0.f, 0.f};
#pragma unroll
    for (int rr = 0; rr < 8; rr++) {
        int row = r0 + rr;
        float wl = 0.f;
#pragma unroll
        for (int c = 0; c < 4; c++) {
            int j = lane * 4 + c;
            wl += tanhf(acc[rr][c] + bsh[j]) * w2sh[j];
        }
        if (row < rows) wl01[row & 1] += wl;
    }
#pragma unroll
    for (int off = 16; off; off >>= 1) {
        wl01[0] += __shfl_xor_sync(0xffffffffu, wl01[0], off);
        wl01[1] += __shfl_xor_sync(0xffffffffu, wl01[1], off);
    }
    if (lane == 0) {
        atomicAdd(&wacc[0], wl01[0]);
        atomicAdd(&wacc[1], wl01[1]);
    }
    __syncthreads();
    if (tid < 2) atomicAdd(&g_wsum[wbase + tid], wacc[tid]);
}

// ---------------- final combine: 0.5*dccf + 0.5*han ----------------
__global__ void __launch_bounds__(256) k_combine(float* __restrict__ out) {
    unsigned i = blockIdx.x * 256u + threadIdx.x;
    if (i >= (unsigned)(NN * DD)) return;
    unsigned node = i >> 6, d = i & 63u;
    float w0, w1;
    size_t zr;
    if (node < NU) {
        w0 = g_wsum[0] * (1.f / NU);
        w1 = g_wsum[1] * (1.f / NU);
        zr = (size_t)node * 128;
    } else {
        w0 = g_wsum[2] * (1.f / NI);
        w1 = g_wsum[3] * (1.f / NI);
        zr = (size_t)NU * 128 + (size_t)(node - NU) * 128;
    }
    float mx = fmaxf(w0, w1);
    float e0 = __expf(w0 - mx), e1 = __expf(w1 - mx);
    float inv = 1.f / (e0 + e1);
    float han = (e0 * inv) * g_z[zr + d] + (e1 * inv) * g_z[zr + 64 + d];
    out[i] = 0.5f * g_total[i] + 0.5f * han;
}

// ---------------- launcher ----------------
extern "C" void kernel_launch(void* const* d_in, const int* in_sizes, int n_in,
                              void* d_out, int out_size) {
    const int*   G    = (const int*)d_in[0];
    const float* Gv   = (const float*)d_in[1];
    const float* fu   = (const float*)d_in[2];
    const float* fi   = (const float*)d_in[3];
    const float* Wu   = (const float*)d_in[4];
    const float* Wi   = (const float*)d_in[5];
    const int*   eu   = (const int*)d_in[6];
    const int*   ei   = (const int*)d_in[7];
    const float* suW1 = (const float*)d_in[8];
    const float* sub1 = (const float*)d_in[9];
    const float* suw2 = (const float*)d_in[10];
    const float* siW1 = (const float*)d_in[11];
    const float* sib1 = (const float*)d_in[12];
    const float* siw2 = (const float*)d_in[13];
    float* out = (float*)d_out;

    cudaFuncSetAttribute(k_intent, cudaFuncAttributeMaxDynamicSharedMemorySize, INTENT_SMEM);

    const int UB = (NU + IT_ROWS_PER_BLOCK - 1) / IT_ROWS_PER_BLOCK;  // 2084
    const int IB = (NI + IT_ROWS_PER_BLOCK - 1) / IT_ROWS_PER_BLOCK;  // 1042

    k_init<<<37500, 256>>>(fu, fi);
    for (int layer = 0; layer < 2; layer++) {
        k_zero_gnn<<<37500, 256>>>();
        k_spmm<<<200000, 256>>>(G, Gv);
        k_intent<<<UB + IB, IT_THREADS, INTENT_SMEM>>>(Wu, Wi);
    }
    k_zero_han<<<75000, 256>>>();
    k_deg<<<12500, 256>>>(eu, EU_, NU, 0);
    k_deg<<<6250, 256>>>(ei, EI_, NI, NU * 4);
    k_scatter<<<200000, 256>>>(eu, EU_, NU, 0, 0, fu);
    k_scatter<<<100000, 256>>>(ei, EI_, NI, NU * 4, NU * 128, fi);
    k_han_node<<<3125, 256>>>(suW1, sub1, suw2, NU, 0, 0, 0);
    k_han_node<<<1563, 256>>>(siW1, sib1, siw2, NI, NU * 4, NU * 128, 2);
    k_combine<<<37500, 256>>>(out);
}